// round 9
// baseline (speedup 1.0000x reference)
#include <cuda_runtime.h>
#include <cstdint>

// FastText embedding-bag:
//   out[b,:] = W_in[center_ids[b],:] + sum_{i: seg[i]==b} W_sub[ngram_idx[i],:]
// seg sorted ascending. D = 300 floats = 75 float4 per row (1200 B).
//
// R9: single kernel. Bag range via INTERPOLATED warp search:
//     seg ~ sorted uniform -> lower_bound(b) ~ b*total/B +- ~300 (3sigma ~900).
//     Round 0 probes a +-1024 window at stride 64 (one round replaces three),
//     then the proven 32-ary loop finishes in ~2 near-coalesced rounds.
//     Row pipeline unchanged (best known): cp.async ring, 8 rows, 2 rows/group.

#define D4    75
#define CHUNK 64

// ---------------------------------------------------------------- helpers
__device__ __forceinline__ uint32_t smem_u32(const void* p)
{
    return (uint32_t)__cvta_generic_to_shared(p);
}
__device__ __forceinline__ void cp16(uint32_t s, const void* g)
{
    asm volatile("cp.async.cg.shared.global [%0], [%1], 16;\n" :: "r"(s), "l"(g));
}
__device__ __forceinline__ void cp_commit()
{
    asm volatile("cp.async.commit_group;\n" ::: "memory");
}
__device__ __forceinline__ void cp_wait3()
{
    asm volatile("cp.async.wait_group 3;\n" ::: "memory");
}

// warp-cooperative lower_bound with interpolated first round.
// invariant maintained: lb in [lo, hi] (loop returns lo when lo==hi).
__device__ __forceinline__ int warp_lower_bound(const int* __restrict__ seg,
                                                int total, int target, int lane,
                                                int guess)
{
    int lo = 0, hi = total;

    // ---- round 0: +-1024 window around guess, stride 64 ----
    int w0 = guess - 1024;
    if (w0 > total - 2048) w0 = total - 2048;
    if (w0 < 0) w0 = 0;
    {
        const int pos = w0 + lane * 64;
        const bool pred = (pos < total) && (__ldg(seg + pos) < target);
        const unsigned m = __ballot_sync(0xFFFFFFFFu, pred);
        if (m == 0u) {
            hi = w0;                     // seg[w0] >= target -> lb <= w0 (rare unless w0==0)
        } else {
            const int hsb = 31 - __clz(m);
            lo = w0 + hsb * 64 + 1;      // seg at hsb probe < target
            if (hsb < 31) {
                const int nh = w0 + (hsb + 1) * 64;
                if (nh < hi) hi = nh;    // probe hsb+1 (or OOR=+inf) was >= target
            }                            // hsb==31: window miss right -> keep hi=total
        }
    }

    // ---- general 32-ary rounds (proven in R8) ----
    while (hi > lo) {
        const int step = (hi - lo + 31) >> 5;
        const int pos  = lo + lane * step;
        const bool pred = (pos < hi) && (__ldg(seg + pos) < target);
        const unsigned m = __ballot_sync(0xFFFFFFFFu, pred);
        if (m == 0u) { hi = lo; break; }                // seg[lo] >= target -> lb = lo
        const int hsb = 31 - __clz(m);
        const int nlo = lo + hsb * step + 1;
        const int nhi = lo + (hsb + 1) * step;
        if (nhi < hi) hi = nhi;
        lo = nlo;
    }
    return lo;
}

// ---------------------------------------------------------------- gather
__global__ void __launch_bounds__(96)
ft_bag_kernel(const int* __restrict__ center,
              const int* __restrict__ ngram,
              const int* __restrict__ seg,
              const float4* __restrict__ Win,
              const float4* __restrict__ Wsub,
              float4* __restrict__ out,
              int total, int B)
{
    const int b = blockIdx.x;
    const int t = threadIdx.x;
    const int w = t >> 5;
    const int lane = t & 31;
    const bool act = (t < D4);

    __shared__ int    s_lo, s_hi;
    __shared__ int    s_idx[CHUNK];       // pre-scaled: ngram * D4
    __shared__ float4 ring[8 * D4];       // 4 groups x 2 rows

    // wv gather issued first — its DRAM latency covers the search below
    float4 acc = make_float4(0.f, 0.f, 0.f, 0.f);
    if (act) {
        const int crow = __ldg(center + b) * D4;
        acc = __ldg(Win + crow + t);
    }

    // warp 0 -> lower_bound(b), warp 1 -> lower_bound(b+1)
    if (w < 2) {
        const int target = b + w;
        const int guess  = (int)(((long long)target * total) / B);
        const int r = warp_lower_bound(seg, total, target, lane, guess);
        if (lane == 0) { if (w == 0) s_lo = r; else s_hi = r; }
    }
    __syncthreads();

    const int lo = s_lo;
    const int hi = s_hi;

    const uint32_t my0   = smem_u32(ring) + (uint32_t)t * 16u;
    const uint32_t rowSz = D4 * 16u;

    for (int base = lo; base < hi; base += CHUNK) {
        const int n = min(hi - base, CHUNK);

        if (base != lo) __syncthreads();
        if (t < n) s_idx[t] = __ldg(ngram + base + t) * D4;
        __syncthreads();

        if (act) {
            // prologue: 4 groups x 2 rows (rows 0..7), uniform predicates
            #pragma unroll
            for (int g = 0; g < 4; ++g) {
                const int k0 = 2 * g, k1 = 2 * g + 1;
                if (k0 < n) cp16(my0 + (uint32_t)k0 * rowSz, Wsub + s_idx[k0] + t);
                if (k1 < n) cp16(my0 + (uint32_t)k1 * rowSz, Wsub + s_idx[k1] + t);
                cp_commit();
            }

            // steady state: consume rows (j, j+1), refill rows (j+8, j+9)
            #pragma unroll 1
            for (int j = 0; j < n; j += 2) {
                cp_wait3();                        // group j/2 complete
                const int s0 = (j & 7);
                float4 v0 = ring[s0 * D4 + t];
                float4 v1 = make_float4(0.f, 0.f, 0.f, 0.f);
                if (j + 1 < n) v1 = ring[(s0 + 1) * D4 + t];
                acc.x += v0.x + v1.x;
                acc.y += v0.y + v1.y;
                acc.z += v0.z + v1.z;
                acc.w += v0.w + v1.w;              // FADDs order LDS before refill

                const int k0 = j + 8, k1 = j + 9;
                if (k0 < n) cp16(my0 + (uint32_t)s0 * rowSz,       Wsub + s_idx[k0] + t);
                if (k1 < n) cp16(my0 + (uint32_t)(s0 + 1) * rowSz, Wsub + s_idx[k1] + t);
                cp_commit();                       // keeps group count aligned
            }
        }
    }

    if (act) out[b * D4 + t] = acc;
}

extern "C" void kernel_launch(void* const* d_in, const int* in_sizes, int n_in,
                              void* d_out, int out_size)
{
    const int*    center = (const int*)d_in[0];
    const int*    ngram  = (const int*)d_in[1];
    const int*    seg    = (const int*)d_in[2];
    const float4* Win    = (const float4*)d_in[3];
    const float4* Wsub   = (const float4*)d_in[4];
    float4*       out    = (float4*)d_out;

    const int B     = in_sizes[0];
    const int total = in_sizes[1];

    ft_bag_kernel<<<B, 96>>>(center, ngram, seg, Win, Wsub, out, total, B);
}